// round 1
// baseline (speedup 1.0000x reference)
#include <cuda_runtime.h>

#define T_STEPS 128
#define BATCH   64
#define DFEAT   32
#define NSUP    1024
#define MROWS   8192   // T_STEPS*BATCH
#define LSTM_BLOCKS 16
#define TILES_M 64
#define TILES_N 8
#define NBLOCKS (LSTM_BLOCKS + TILES_M*TILES_N)

#define OUTS_OFF 0
#define RBF_OFF  32768
#define QK_OFF   (32768 + MROWS*NSUP)

__device__ __forceinline__ float sigm_fast(float z){
    float e = __expf(-z);
    return __fdividef(1.0f, 1.0f + e);
}
__device__ __forceinline__ float tanh_fast(float z){
    float e = __expf(-2.0f*z);
    return __fdividef(1.0f - e, 1.0f + e);
}
__device__ __forceinline__ void fma4(float4& d, float a, const float4& b){
    d.x = fmaf(a, b.x, d.x);
    d.y = fmaf(a, b.y, d.y);
    d.z = fmaf(a, b.z, d.z);
    d.w = fmaf(a, b.w, d.w);
}

__global__ __launch_bounds__(256, 2)
void hyb_kernel(const float* __restrict__ x,
                const float* __restrict__ sv,
                const float* __restrict__ Wf, const float* __restrict__ bf,
                const float* __restrict__ Wi, const float* __restrict__ bi,
                const float* __restrict__ Wu, const float* __restrict__ bu,
                const float* __restrict__ Wo, const float* __restrict__ bo,
                const float* __restrict__ pf, const float* __restrict__ pi,
                const float* __restrict__ pu, const float* __restrict__ po,
                const float* __restrict__ qkp,
                float* __restrict__ out)
{
    if (blockIdx.x < LSTM_BLOCKS) {
        // ================= LSTM role: one warp per batch element =================
        int warp = threadIdx.x >> 5;
        if (warp >= 4) return;
        int lane = threadIdx.x & 31;
        int b    = blockIdx.x * 4 + warp;
        int sl   = lane & 15;
        int g    = sl >> 2;   // 0=f 1=i 2=u 3=o
        int w    = sl & 3;    // wire / hidden index

        const float* W  = (g==0)?Wf:(g==1)?Wi:(g==2)?Wu:Wo;
        const float* bb = (g==0)?bf:(g==1)?bi:(g==2)?bu:bo;
        const float* pp = (g==0)?pf:(g==1)?pi:(g==2)?pu:po;

        float wx[32];
        #pragma unroll
        for (int d=0; d<32; d++) wx[d] = W[w*36 + d];
        float wh0 = W[w*36+32], wh1 = W[w*36+33], wh2 = W[w*36+34], wh3 = W[w*36+35];
        float bias = bb[w] + pp[w];   // fold param angle into bias (RX compose)

        float h0=0.f,h1=0.f,h2=0.f,h3=0.f,cst=0.f;
        const unsigned FULL = 0xffffffffu;

        // dot of x_t with Wx for t=0
        float dcur;
        {
            const float4* xp = (const float4*)(x + (size_t)b*DFEAT);
            float s0=bias, s1=0.f, s2=0.f, s3=0.f;
            #pragma unroll
            for (int q=0;q<8;q++){
                float4 v = xp[q];
                s0 = fmaf(wx[4*q+0], v.x, s0);
                s1 = fmaf(wx[4*q+1], v.y, s1);
                s2 = fmaf(wx[4*q+2], v.z, s2);
                s3 = fmaf(wx[4*q+3], v.w, s3);
            }
            dcur = (s0+s1)+(s2+s3);
        }

        for (int t=0; t<T_STEPS; t++){
            float theta = dcur;
            theta = fmaf(wh0,h0,theta);
            theta = fmaf(wh1,h1,theta);
            theta = fmaf(wh2,h2,theta);
            theta = fmaf(wh3,h3,theta);
            float cth = __cosf(theta);

            // off-critical-path: compute next step's x-dot while recurrent chain runs
            float dnext = bias;
            if (t < T_STEPS-1){
                const float4* xp = (const float4*)(x + ((size_t)(t+1)*BATCH + b)*DFEAT);
                float s0=bias, s1=0.f, s2=0.f, s3=0.f;
                #pragma unroll
                for (int q=0;q<8;q++){
                    float4 v = __ldg(&xp[q]);
                    s0 = fmaf(wx[4*q+0], v.x, s0);
                    s1 = fmaf(wx[4*q+1], v.y, s1);
                    s2 = fmaf(wx[4*q+2], v.z, s2);
                    s3 = fmaf(wx[4*q+3], v.w, s3);
                }
                dnext = (s0+s1)+(s2+s3);
            }

            int base = lane & ~3;
            float c0 = __shfl_sync(FULL, cth, base+0);
            float c1 = __shfl_sync(FULL, cth, base+1);
            float c2 = __shfl_sync(FULL, cth, base+2);
            float c3 = __shfl_sync(FULL, cth, base+3);
            float p01  = c0*c1;
            float p012 = p01*c2;
            float z = (w==0) ? c1*c2*c3 : (w==1) ? p01 : (w==2) ? p012 : p012*c3;
            float val = (g==2) ? tanh_fast(z) : sigm_fast(z);

            int hb = lane & 16;
            float fv = __shfl_sync(FULL, val, hb + 0  + w);
            float iv = __shfl_sync(FULL, val, hb + 4  + w);
            float uv = __shfl_sync(FULL, val, hb + 8  + w);
            float ov = __shfl_sync(FULL, val, hb + 12 + w);

            cst = fmaf(fv, cst, iv*uv);
            float ht = ov * tanh_fast(cst);
            if (lane < 4) out[OUTS_OFF + t*(BATCH*4) + b*4 + w] = ht;

            h0 = __shfl_sync(FULL, ht, base+0);
            h1 = __shfl_sync(FULL, ht, base+1);
            h2 = __shfl_sync(FULL, ht, base+2);
            h3 = __shfl_sync(FULL, ht, base+3);
            dcur = dnext;
        }
        return;
    }

    // ================= rbf + qk tile role: 128x128 tile per block =================
    __shared__ __align__(16) float xs[32][132];   // k-major x tile (m in 0..127)
    __shared__ __align__(16) float ss[32][132];   // k-major s tile
    __shared__ float xrow[128][10];               // cos u[4], sin u[4], ||x||^2
    __shared__ float srow[128][10];               // cos v[4], sin v[4], ||s||^2

    int tile = blockIdx.x - LSTM_BLOCKS;
    int mt = tile >> 3;
    int nt = tile & 7;
    int m0 = mt * 128;
    int n0 = nt * 128;
    int tid = threadIdx.x;

    {   // load both tiles transposed into smem (coalesced gmem reads)
        int rbase = tid >> 3;          // 0..31
        int kc    = (tid & 7) * 4;     // k chunk
        #pragma unroll
        for (int pass=0; pass<4; pass++){
            int r = rbase + pass*32;
            float4 v = *(const float4*)(x  + (size_t)(m0 + r)*DFEAT + kc);
            xs[kc+0][r]=v.x; xs[kc+1][r]=v.y; xs[kc+2][r]=v.z; xs[kc+3][r]=v.w;
            float4 u = *(const float4*)(sv + (size_t)(n0 + r)*DFEAT + kc);
            ss[kc+0][r]=u.x; ss[kc+1][r]=u.y; ss[kc+2][r]=u.z; ss[kc+3][r]=u.w;
        }
    }
    __syncthreads();

    {   // per-row factors: norms + sincos((feat + qkp)/2)
        int r = tid & 127;
        float (*rowArr)[10]  = (tid < 128) ? xrow : srow;
        float (*tileArr)[132] = (tid < 128) ? xs : ss;
        float nrm = 0.f;
        #pragma unroll
        for (int k=0;k<32;k++){ float v = tileArr[k][r]; nrm = fmaf(v,v,nrm); }
        #pragma unroll
        for (int w=0; w<4; w++){
            float th = fmaf(tileArr[w][r], 0.5f, qkp[w]*0.5f);
            float s_, c_;
            sincosf(th, &s_, &c_);
            rowArr[r][w]   = c_;
            rowArr[r][4+w] = s_;
        }
        rowArr[r][8] = nrm;
    }
    __syncthreads();

    int tx = tid & 15;        // 16 col-groups
    int ty = tid >> 4;        // 16 row-groups
    // thread covers rows {ty*4+r + 64*ii} and cols {tx*4+c + 64*jj}
    float4 acc[2][4][2];
    #pragma unroll
    for (int ii=0; ii<2; ii++)
        #pragma unroll
        for (int r=0; r<4; r++)
            #pragma unroll
            for (int jj=0; jj<2; jj++)
                acc[ii][r][jj] = make_float4(0.f,0.f,0.f,0.f);

    #pragma unroll 8
    for (int k=0; k<32; k++){
        const float4* xr = (const float4*)xs[k];
        const float4* sr = (const float4*)ss[k];
        float4 a0 = xr[ty];
        float4 a1 = xr[ty+16];
        float4 b0 = sr[tx];
        float4 b1 = sr[tx+16];
        fma4(acc[0][0][0], a0.x, b0); fma4(acc[0][0][1], a0.x, b1);
        fma4(acc[0][1][0], a0.y, b0); fma4(acc[0][1][1], a0.y, b1);
        fma4(acc[0][2][0], a0.z, b0); fma4(acc[0][2][1], a0.z, b1);
        fma4(acc[0][3][0], a0.w, b0); fma4(acc[0][3][1], a0.w, b1);
        fma4(acc[1][0][0], a1.x, b0); fma4(acc[1][0][1], a1.x, b1);
        fma4(acc[1][1][0], a1.y, b0); fma4(acc[1][1][1], a1.y, b1);
        fma4(acc[1][2][0], a1.z, b0); fma4(acc[1][2][1], a1.z, b1);
        fma4(acc[1][3][0], a1.w, b0); fma4(acc[1][3][1], a1.w, b1);
    }

    float* rbf_out = out + RBF_OFF;
    float* qk_out  = out + QK_OFF;
    const int ncol0 = n0 + tx*4;

    // ---- phase 1: rbf = exp(2*dot - ||x||^2 - ||s||^2) ----
    {
        float snA[4], snB[4];
        #pragma unroll
        for (int c=0;c<4;c++){ snA[c]=srow[tx*4+c][8]; snB[c]=srow[tx*4+c+64][8]; }
        #pragma unroll
        for (int ii=0; ii<2; ii++){
            #pragma unroll
            for (int r=0; r<4; r++){
                int mi = ty*4 + r + 64*ii;
                float xn = xrow[mi][8];
                int m = m0 + mi;
                float4 o0, o1;
                o0.x = __expf(fmaf(2.f, acc[ii][r][0].x, -(xn+snA[0])));
                o0.y = __expf(fmaf(2.f, acc[ii][r][0].y, -(xn+snA[1])));
                o0.z = __expf(fmaf(2.f, acc[ii][r][0].z, -(xn+snA[2])));
                o0.w = __expf(fmaf(2.f, acc[ii][r][0].w, -(xn+snA[3])));
                o1.x = __expf(fmaf(2.f, acc[ii][r][1].x, -(xn+snB[0])));
                o1.y = __expf(fmaf(2.f, acc[ii][r][1].y, -(xn+snB[1])));
                o1.z = __expf(fmaf(2.f, acc[ii][r][1].z, -(xn+snB[2])));
                o1.w = __expf(fmaf(2.f, acc[ii][r][1].w, -(xn+snB[3])));
                *(float4*)(rbf_out + (size_t)m*NSUP + ncol0)      = o0;
                *(float4*)(rbf_out + (size_t)m*NSUP + ncol0 + 64) = o1;
            }
        }
    }

    // ---- phase 2: qk[m,n] = | prod_w cos(u_mw + v_nw) | ----
    {
        float cvA[4][4], svA[4][4], cvB[4][4], svB[4][4];
        #pragma unroll
        for (int c=0;c<4;c++){
            #pragma unroll
            for (int w=0;w<4;w++){
                cvA[c][w]=srow[tx*4+c][w];    svA[c][w]=srow[tx*4+c][4+w];
                cvB[c][w]=srow[tx*4+c+64][w]; svB[c][w]=srow[tx*4+c+64][4+w];
            }
        }
        #pragma unroll
        for (int ii=0; ii<2; ii++){
            #pragma unroll
            for (int r=0; r<4; r++){
                int mi = ty*4 + r + 64*ii;
                float cu[4], su[4];
                #pragma unroll
                for (int w=0;w<4;w++){ cu[w]=xrow[mi][w]; su[w]=xrow[mi][4+w]; }
                int m = m0 + mi;
                float q0[4], q1[4];
                #pragma unroll
                for (int c=0;c<4;c++){
                    float t0 = fmaf(cu[0], cvA[c][0], -(su[0]*svA[c][0]));
                    float t1 = fmaf(cu[1], cvA[c][1], -(su[1]*svA[c][1]));
                    float t2 = fmaf(cu[2], cvA[c][2], -(su[2]*svA[c][2]));
                    float t3 = fmaf(cu[3], cvA[c][3], -(su[3]*svA[c][3]));
                    q0[c] = fabsf((t0*t1)*(t2*t3));
                    float u0 = fmaf(cu[0], cvB[c][0], -(su[0]*svB[c][0]));
                    float u1 = fmaf(cu[1], cvB[c][1], -(su[1]*svB[c][1]));
                    float u2 = fmaf(cu[2], cvB[c][2], -(su[2]*svB[c][2]));
                    float u3 = fmaf(cu[3], cvB[c][3], -(su[3]*svB[c][3]));
                    q1[c] = fabsf((u0*u1)*(u2*u3));
                }
                *(float4*)(qk_out + (size_t)m*NSUP + ncol0)      = make_float4(q0[0],q0[1],q0[2],q0[3]);
                *(float4*)(qk_out + (size_t)m*NSUP + ncol0 + 64) = make_float4(q1[0],q1[1],q1[2],q1[3]);
            }
        }
    }
}

extern "C" void kernel_launch(void* const* d_in, const int* in_sizes, int n_in,
                              void* d_out, int out_size)
{
    const float* x   = (const float*)d_in[0];
    const float* sv  = (const float*)d_in[1];
    const float* Wf  = (const float*)d_in[2];
    const float* bf  = (const float*)d_in[3];
    const float* Wi  = (const float*)d_in[4];
    const float* bi  = (const float*)d_in[5];
    const float* Wu  = (const float*)d_in[6];
    const float* bu  = (const float*)d_in[7];
    const float* Wo  = (const float*)d_in[8];
    const float* bo  = (const float*)d_in[9];
    const float* pf  = (const float*)d_in[10];
    const float* pi_ = (const float*)d_in[11];
    const float* pu  = (const float*)d_in[12];
    const float* po  = (const float*)d_in[13];
    const float* qkp = (const float*)d_in[14];

    hyb_kernel<<<NBLOCKS, 256>>>(x, sv, Wf, bf, Wi, bi, Wu, bu, Wo, bo,
                                 pf, pi_, pu, po, qkp, (float*)d_out);
}

// round 2
// speedup vs baseline: 1.0253x; 1.0253x over previous
#include <cuda_runtime.h>

#define T_STEPS 128
#define BATCH   64
#define DFEAT   32
#define NSUP    1024
#define MROWS   8192   // T_STEPS*BATCH
#define LSTM_BLOCKS 16
#define TILES_M 64
#define TILES_N 8
#define NBLOCKS (LSTM_BLOCKS + TILES_M*TILES_N)

#define OUTS_OFF 0
#define RBF_OFF  32768
#define QK_OFF   (32768 + MROWS*NSUP)

__device__ __forceinline__ float sigm_fast(float z){
    float e = __expf(-z);
    return __fdividef(1.0f, 1.0f + e);
}
__device__ __forceinline__ float tanh_fast(float z){
    float e = __expf(-2.0f*z);
    return __fdividef(1.0f - e, 1.0f + e);
}
__device__ __forceinline__ void fma4(float4& d, float a, const float4& b){
    d.x = fmaf(a, b.x, d.x);
    d.y = fmaf(a, b.y, d.y);
    d.z = fmaf(a, b.z, d.z);
    d.w = fmaf(a, b.w, d.w);
}

// All-FMA/ALU expf replacement (no MUFU). |rel err| ~1e-7 on [-87, 1].
// Round via magic constant; exponent extracted from the magic float's bits
// (no F2I). Clamp matches expf underflow-to-zero region closely enough.
__device__ __forceinline__ float fast_exp(float x){
    x = fmaxf(x, -87.0f);
    float t = fmaf(x, 1.4426950408889634f, 12582912.0f); // 3*2^22
    float n = t - 12582912.0f;
    float f = fmaf(n, -0.693147182464599609375f, x);     // ln2_hi (float)
    f = fmaf(n, 1.9046542743e-9f, f);                    // ln2_hi - ln2 correction
    float z = f * f;
    float p = 1.9875691500E-4f;
    p = fmaf(p, f, 1.3981999507E-3f);
    p = fmaf(p, f, 8.3334519073E-3f);
    p = fmaf(p, f, 4.1665795894E-2f);
    p = fmaf(p, f, 1.6666665459E-1f);
    p = fmaf(p, f, 5.0000001201E-1f);
    p = fmaf(p, z, f);
    p += 1.0f;
    // bits(t) = 0x4B400000 + (int)n  for |n| < 2^22
    int bi = __float_as_int(t);
    float s = __int_as_float((bi + (127 - 0x4B400000)) << 23);
    return p * s;
}

__global__ __launch_bounds__(256, 2)
void hyb_kernel(const float* __restrict__ x,
                const float* __restrict__ sv,
                const float* __restrict__ Wf, const float* __restrict__ bf,
                const float* __restrict__ Wi, const float* __restrict__ bi,
                const float* __restrict__ Wu, const float* __restrict__ bu,
                const float* __restrict__ Wo, const float* __restrict__ bo,
                const float* __restrict__ pf, const float* __restrict__ pi,
                const float* __restrict__ pu, const float* __restrict__ po,
                const float* __restrict__ qkp,
                float* __restrict__ out)
{
    if (blockIdx.x < LSTM_BLOCKS) {
        // ================= LSTM role: one warp per batch element =================
        int warp = threadIdx.x >> 5;
        if (warp >= 4) return;
        int lane = threadIdx.x & 31;
        int b    = blockIdx.x * 4 + warp;
        int sl   = lane & 15;
        int g    = sl >> 2;   // 0=f 1=i 2=u 3=o
        int w    = sl & 3;    // wire / hidden index

        const float* W  = (g==0)?Wf:(g==1)?Wi:(g==2)?Wu:Wo;
        const float* bb = (g==0)?bf:(g==1)?bi:(g==2)?bu:bo;
        const float* pp = (g==0)?pf:(g==1)?pi:(g==2)?pu:po;

        float wx[32];
        #pragma unroll
        for (int d=0; d<32; d++) wx[d] = W[w*36 + d];
        float wh0 = W[w*36+32], wh1 = W[w*36+33], wh2 = W[w*36+34], wh3 = W[w*36+35];
        float bias = bb[w] + pp[w];   // fold param angle into bias (RX compose)

        float h0=0.f,h1=0.f,h2=0.f,h3=0.f,cst=0.f;
        const unsigned FULL = 0xffffffffu;

        // dot of x_t with Wx for t=0
        float dcur;
        {
            const float4* xp = (const float4*)(x + (size_t)b*DFEAT);
            float s0=bias, s1=0.f, s2=0.f, s3=0.f;
            #pragma unroll
            for (int q=0;q<8;q++){
                float4 v = xp[q];
                s0 = fmaf(wx[4*q+0], v.x, s0);
                s1 = fmaf(wx[4*q+1], v.y, s1);
                s2 = fmaf(wx[4*q+2], v.z, s2);
                s3 = fmaf(wx[4*q+3], v.w, s3);
            }
            dcur = (s0+s1)+(s2+s3);
        }

        for (int t=0; t<T_STEPS; t++){
            float theta = dcur;
            theta = fmaf(wh0,h0,theta);
            theta = fmaf(wh1,h1,theta);
            theta = fmaf(wh2,h2,theta);
            theta = fmaf(wh3,h3,theta);
            float cth = __cosf(theta);

            // off-critical-path: compute next step's x-dot while recurrent chain runs
            float dnext = bias;
            if (t < T_STEPS-1){
                const float4* xp = (const float4*)(x + ((size_t)(t+1)*BATCH + b)*DFEAT);
                float s0=bias, s1=0.f, s2=0.f, s3=0.f;
                #pragma unroll
                for (int q=0;q<8;q++){
                    float4 v = __ldg(&xp[q]);
                    s0 = fmaf(wx[4*q+0], v.x, s0);
                    s1 = fmaf(wx[4*q+1], v.y, s1);
                    s2 = fmaf(wx[4*q+2], v.z, s2);
                    s3 = fmaf(wx[4*q+3], v.w, s3);
                }
                dnext = (s0+s1)+(s2+s3);
            }

            int base = lane & ~3;
            float c0 = __shfl_sync(FULL, cth, base+0);
            float c1 = __shfl_sync(FULL, cth, base+1);
            float c2 = __shfl_sync(FULL, cth, base+2);
            float c3 = __shfl_sync(FULL, cth, base+3);
            float p01  = c0*c1;
            float p012 = p01*c2;
            float z = (w==0) ? c1*c2*c3 : (w==1) ? p01 : (w==2) ? p012 : p012*c3;
            float val = (g==2) ? tanh_fast(z) : sigm_fast(z);

            int hb = lane & 16;
            float fv = __shfl_sync(FULL, val, hb + 0  + w);
            float iv = __shfl_sync(FULL, val, hb + 4  + w);
            float uv = __shfl_sync(FULL, val, hb + 8  + w);
            float ov = __shfl_sync(FULL, val, hb + 12 + w);

            cst = fmaf(fv, cst, iv*uv);
            float ht = ov * tanh_fast(cst);
            if (lane < 4) out[OUTS_OFF + t*(BATCH*4) + b*4 + w] = ht;

            h0 = __shfl_sync(FULL, ht, base+0);
            h1 = __shfl_sync(FULL, ht, base+1);
            h2 = __shfl_sync(FULL, ht, base+2);
            h3 = __shfl_sync(FULL, ht, base+3);
            dcur = dnext;
        }
        return;
    }

    // ================= rbf + qk tile role: 128x128 tile per block =================
    __shared__ __align__(16) float xs[32][132];   // k-major x tile (m in 0..127)
    __shared__ __align__(16) float ss[32][132];   // k-major s tile
    __shared__ float xrow[128][10];               // cos u[4], sin u[4], ||x||^2
    __shared__ float srow[128][10];               // cos v[4], sin v[4], ||s||^2

    int tile = blockIdx.x - LSTM_BLOCKS;
    int mt = tile >> 3;
    int nt = tile & 7;
    int m0 = mt * 128;
    int n0 = nt * 128;
    int tid = threadIdx.x;

    {   // load both tiles transposed into smem (coalesced gmem reads)
        int rbase = tid >> 3;          // 0..31
        int kc    = (tid & 7) * 4;     // k chunk
        #pragma unroll
        for (int pass=0; pass<4; pass++){
            int r = rbase + pass*32;
            float4 v = *(const float4*)(x  + (size_t)(m0 + r)*DFEAT + kc);
            xs[kc+0][r]=v.x; xs[kc+1][r]=v.y; xs[kc+2][r]=v.z; xs[kc+3][r]=v.w;
            float4 u = *(const float4*)(sv + (size_t)(n0 + r)*DFEAT + kc);
            ss[kc+0][r]=u.x; ss[kc+1][r]=u.y; ss[kc+2][r]=u.z; ss[kc+3][r]=u.w;
        }
    }
    __syncthreads();

    {   // per-row factors: norms + sincos((feat + qkp)/2)
        int r = tid & 127;
        float (*rowArr)[10]  = (tid < 128) ? xrow : srow;
        float (*tileArr)[132] = (tid < 128) ? xs : ss;
        float nrm = 0.f;
        #pragma unroll
        for (int k=0;k<32;k++){ float v = tileArr[k][r]; nrm = fmaf(v,v,nrm); }
        #pragma unroll
        for (int w=0; w<4; w++){
            float th = fmaf(tileArr[w][r], 0.5f, qkp[w]*0.5f);
            float s_, c_;
            sincosf(th, &s_, &c_);
            rowArr[r][w]   = c_;
            rowArr[r][4+w] = s_;
        }
        rowArr[r][8] = nrm;
    }
    __syncthreads();

    int tx = tid & 15;        // 16 col-groups
    int ty = tid >> 4;        // 16 row-groups
    // thread covers rows {ty*4+r + 64*ii} and cols {tx*4+c + 64*jj}
    float4 acc[2][4][2];
    #pragma unroll
    for (int ii=0; ii<2; ii++)
        #pragma unroll
        for (int r=0; r<4; r++)
            #pragma unroll
            for (int jj=0; jj<2; jj++)
                acc[ii][r][jj] = make_float4(0.f,0.f,0.f,0.f);

    #pragma unroll 8
    for (int k=0; k<32; k++){
        const float4* xr = (const float4*)xs[k];
        const float4* sr = (const float4*)ss[k];
        float4 a0 = xr[ty];
        float4 a1 = xr[ty+16];
        float4 b0 = sr[tx];
        float4 b1 = sr[tx+16];
        fma4(acc[0][0][0], a0.x, b0); fma4(acc[0][0][1], a0.x, b1);
        fma4(acc[0][1][0], a0.y, b0); fma4(acc[0][1][1], a0.y, b1);
        fma4(acc[0][2][0], a0.z, b0); fma4(acc[0][2][1], a0.z, b1);
        fma4(acc[0][3][0], a0.w, b0); fma4(acc[0][3][1], a0.w, b1);
        fma4(acc[1][0][0], a1.x, b0); fma4(acc[1][0][1], a1.x, b1);
        fma4(acc[1][1][0], a1.y, b0); fma4(acc[1][1][1], a1.y, b1);
        fma4(acc[1][2][0], a1.z, b0); fma4(acc[1][2][1], a1.z, b1);
        fma4(acc[1][3][0], a1.w, b0); fma4(acc[1][3][1], a1.w, b1);
    }

    float* rbf_out = out + RBF_OFF;
    float* qk_out  = out + QK_OFF;
    const int ncol0 = n0 + tx*4;

    // ---- phase 1: rbf = exp(2*dot - ||x||^2 - ||s||^2) ----
    {
        float snA[4], snB[4];
        #pragma unroll
        for (int c=0;c<4;c++){ snA[c]=srow[tx*4+c][8]; snB[c]=srow[tx*4+c+64][8]; }
        #pragma unroll
        for (int ii=0; ii<2; ii++){
            #pragma unroll
            for (int r=0; r<4; r++){
                int mi = ty*4 + r + 64*ii;
                float xn = xrow[mi][8];
                int m = m0 + mi;
                float4 o0, o1;
                o0.x = fast_exp(fmaf(2.f, acc[ii][r][0].x, -(xn+snA[0])));
                o0.y = fast_exp(fmaf(2.f, acc[ii][r][0].y, -(xn+snA[1])));
                o0.z = fast_exp(fmaf(2.f, acc[ii][r][0].z, -(xn+snA[2])));
                o0.w = fast_exp(fmaf(2.f, acc[ii][r][0].w, -(xn+snA[3])));
                o1.x = fast_exp(fmaf(2.f, acc[ii][r][1].x, -(xn+snB[0])));
                o1.y = fast_exp(fmaf(2.f, acc[ii][r][1].y, -(xn+snB[1])));
                o1.z = fast_exp(fmaf(2.f, acc[ii][r][1].z, -(xn+snB[2])));
                o1.w = fast_exp(fmaf(2.f, acc[ii][r][1].w, -(xn+snB[3])));
                *(float4*)(rbf_out + (size_t)m*NSUP + ncol0)      = o0;
                *(float4*)(rbf_out + (size_t)m*NSUP + ncol0 + 64) = o1;
            }
        }
    }

    // ---- phase 2: qk[m,n] = | prod_w cos(u_mw + v_nw) | ----
    {
        float cvA[4][4], svA[4][4], cvB[4][4], svB[4][4];
        #pragma unroll
        for (int c=0;c<4;c++){
            #pragma unroll
            for (int w=0;w<4;w++){
                cvA[c][w]=srow[tx*4+c][w];    svA[c][w]=srow[tx*4+c][4+w];
                cvB[c][w]=srow[tx*4+c+64][w]; svB[c][w]=srow[tx*4+c+64][4+w];
            }
        }
        #pragma unroll
        for (int ii=0; ii<2; ii++){
            #pragma unroll
            for (int r=0; r<4; r++){
                int mi = ty*4 + r + 64*ii;
                float cu[4], su[4];
                #pragma unroll
                for (int w=0;w<4;w++){ cu[w]=xrow[mi][w]; su[w]=xrow[mi][4+w]; }
                int m = m0 + mi;
                float q0[4], q1[4];
                #pragma unroll
                for (int c=0;c<4;c++){
                    float t0 = fmaf(cu[0], cvA[c][0], -(su[0]*svA[c][0]));
                    float t1 = fmaf(cu[1], cvA[c][1], -(su[1]*svA[c][1]));
                    float t2 = fmaf(cu[2], cvA[c][2], -(su[2]*svA[c][2]));
                    float t3 = fmaf(cu[3], cvA[c][3], -(su[3]*svA[c][3]));
                    q0[c] = fabsf((t0*t1)*(t2*t3));
                    float u0 = fmaf(cu[0], cvB[c][0], -(su[0]*svB[c][0]));
                    float u1 = fmaf(cu[1], cvB[c][1], -(su[1]*svB[c][1]));
                    float u2 = fmaf(cu[2], cvB[c][2], -(su[2]*svB[c][2]));
                    float u3 = fmaf(cu[3], cvB[c][3], -(su[3]*svB[c][3]));
                    q1[c] = fabsf((u0*u1)*(u2*u3));
                }
                *(float4*)(qk_out + (size_t)m*NSUP + ncol0)      = make_float4(q0[0],q0[1],q0[2],q0[3]);
                *(float4*)(qk_out + (size_t)m*NSUP + ncol0 + 64) = make_float4(q1[0],q1[1],q1[2],q1[3]);
            }
        }
    }
}

extern "C" void kernel_launch(void* const* d_in, const int* in_sizes, int n_in,
                              void* d_out, int out_size)
{
    const float* x   = (const float*)d_in[0];
    const float* sv  = (const float*)d_in[1];
    const float* Wf  = (const float*)d_in[2];
    const float* bf  = (const float*)d_in[3];
    const float* Wi  = (const float*)d_in[4];
    const float* bi  = (const float*)d_in[5];
    const float* Wu  = (const float*)d_in[6];
    const float* bu  = (const float*)d_in[7];
    const float* Wo  = (const float*)d_in[8];
    const float* bo  = (const float*)d_in[9];
    const float* pf  = (const float*)d_in[10];
    const float* pi_ = (const float*)d_in[11];
    const float* pu  = (const float*)d_in[12];
    const float* po  = (const float*)d_in[13];
    const float* qkp = (const float*)d_in[14];

    hyb_kernel<<<NBLOCKS, 256>>>(x, sv, Wf, bf, Wi, bi, Wu, bu, Wo, bo,
                                 pf, pi_, pu, po, qkp, (float*)d_out);
}

// round 3
// speedup vs baseline: 1.1838x; 1.1546x over previous
#include <cuda_runtime.h>

#define T_STEPS 128
#define BATCH   64
#define DFEAT   32
#define NSUP    1024
#define MROWS   8192   // T_STEPS*BATCH
#define LSTM_BLOCKS 16
#define TILES_M 64
#define TILES_N 8
#define NBLOCKS (LSTM_BLOCKS + TILES_M*TILES_N)

#define OUTS_OFF 0
#define RBF_OFF  32768
#define QK_OFF   (32768 + MROWS*NSUP)

__device__ __forceinline__ float tanh_hw(float z){
    float r;
    asm("tanh.approx.f32 %0, %1;" : "=f"(r) : "f"(z));
    return r;
}
__device__ __forceinline__ float sigm_hw(float z){
    return fmaf(0.5f, tanh_hw(0.5f*z), 0.5f);
}
__device__ __forceinline__ void fma4(float4& d, float a, const float4& b){
    d.x = fmaf(a, b.x, d.x);
    d.y = fmaf(a, b.y, d.y);
    d.z = fmaf(a, b.z, d.z);
    d.w = fmaf(a, b.w, d.w);
}

// All-FMA/ALU expf replacement (no MUFU). |rel err| ~1e-7 on [-87, 1].
__device__ __forceinline__ float fast_exp(float x){
    x = fmaxf(x, -87.0f);
    float t = fmaf(x, 1.4426950408889634f, 12582912.0f); // 3*2^22
    float n = t - 12582912.0f;
    float f = fmaf(n, -0.693147182464599609375f, x);     // ln2_hi (float)
    f = fmaf(n, 1.9046542743e-9f, f);                    // ln2 correction
    float z = f * f;
    float p = 1.9875691500E-4f;
    p = fmaf(p, f, 1.3981999507E-3f);
    p = fmaf(p, f, 8.3334519073E-3f);
    p = fmaf(p, f, 4.1665795894E-2f);
    p = fmaf(p, f, 1.6666665459E-1f);
    p = fmaf(p, f, 5.0000001201E-1f);
    p = fmaf(p, z, f);
    p += 1.0f;
    int bi = __float_as_int(t);
    float s = __int_as_float((bi + (127 - 0x4B400000)) << 23);
    return p * s;
}

__global__ __launch_bounds__(256, 2)
void hyb_kernel(const float* __restrict__ x,
                const float* __restrict__ sv,
                const float* __restrict__ Wf, const float* __restrict__ bf,
                const float* __restrict__ Wi, const float* __restrict__ bi,
                const float* __restrict__ Wu, const float* __restrict__ bu,
                const float* __restrict__ Wo, const float* __restrict__ bo,
                const float* __restrict__ pf, const float* __restrict__ pi,
                const float* __restrict__ pu, const float* __restrict__ po,
                const float* __restrict__ qkp,
                float* __restrict__ out)
{
    if (blockIdx.x < LSTM_BLOCKS) {
        // ================= LSTM role: one warp per batch element =================
        int warp = threadIdx.x >> 5;
        if (warp >= 4) return;
        int lane = threadIdx.x & 31;
        int b    = blockIdx.x * 4 + warp;
        int sl   = lane & 15;
        int g    = sl >> 2;   // 0=f 1=i 2=u 3=o
        int w    = sl & 3;    // wire / hidden index

        const float* W  = (g==0)?Wf:(g==1)?Wi:(g==2)?Wu:Wo;
        const float* bb = (g==0)?bf:(g==1)?bi:(g==2)?bu:bo;
        const float* pp = (g==0)?pf:(g==1)?pi:(g==2)?pu:po;

        float wx[32];
        #pragma unroll
        for (int d=0; d<32; d++) wx[d] = W[w*36 + d];
        float wh0 = W[w*36+32], wh1 = W[w*36+33], wh2 = W[w*36+34], wh3 = W[w*36+35];
        float bias = bb[w] + pp[w];   // fold param angle into bias (RX compose)

        float h0=0.f,h1=0.f,h2=0.f,h3=0.f,cst=0.f;
        const unsigned FULL = 0xffffffffu;

        float dcur;
        {
            const float4* xp = (const float4*)(x + (size_t)b*DFEAT);
            float s0=bias, s1=0.f, s2=0.f, s3=0.f;
            #pragma unroll
            for (int q=0;q<8;q++){
                float4 v = xp[q];
                s0 = fmaf(wx[4*q+0], v.x, s0);
                s1 = fmaf(wx[4*q+1], v.y, s1);
                s2 = fmaf(wx[4*q+2], v.z, s2);
                s3 = fmaf(wx[4*q+3], v.w, s3);
            }
            dcur = (s0+s1)+(s2+s3);
        }

        for (int t=0; t<T_STEPS; t++){
            float theta = dcur;
            theta = fmaf(wh0,h0,theta);
            theta = fmaf(wh1,h1,theta);
            theta = fmaf(wh2,h2,theta);
            theta = fmaf(wh3,h3,theta);
            float cth = __cosf(theta);

            // off-critical-path: next step's x-dot while recurrent chain runs
            float dnext = bias;
            if (t < T_STEPS-1){
                const float4* xp = (const float4*)(x + ((size_t)(t+1)*BATCH + b)*DFEAT);
                float s0=bias, s1=0.f, s2=0.f, s3=0.f;
                #pragma unroll
                for (int q=0;q<8;q++){
                    float4 v = __ldg(&xp[q]);
                    s0 = fmaf(wx[4*q+0], v.x, s0);
                    s1 = fmaf(wx[4*q+1], v.y, s1);
                    s2 = fmaf(wx[4*q+2], v.z, s2);
                    s3 = fmaf(wx[4*q+3], v.w, s3);
                }
                dnext = (s0+s1)+(s2+s3);
            }

            int base = lane & ~3;
            float c0 = __shfl_sync(FULL, cth, base+0);
            float c1 = __shfl_sync(FULL, cth, base+1);
            float c2 = __shfl_sync(FULL, cth, base+2);
            float c3 = __shfl_sync(FULL, cth, base+3);
            float p01  = c0*c1;
            float p012 = p01*c2;
            float z = (w==0) ? c1*c2*c3 : (w==1) ? p01 : (w==2) ? p012 : p012*c3;
            float val = (g==2) ? tanh_hw(z) : sigm_hw(z);

            int hb = lane & 16;
            float fv = __shfl_sync(FULL, val, hb + 0  + w);
            float iv = __shfl_sync(FULL, val, hb + 4  + w);
            float uv = __shfl_sync(FULL, val, hb + 8  + w);
            float ov = __shfl_sync(FULL, val, hb + 12 + w);

            cst = fmaf(fv, cst, iv*uv);
            float ht = ov * tanh_hw(cst);
            if (lane < 4) out[OUTS_OFF + t*(BATCH*4) + b*4 + w] = ht;

            h0 = __shfl_sync(FULL, ht, base+0);
            h1 = __shfl_sync(FULL, ht, base+1);
            h2 = __shfl_sync(FULL, ht, base+2);
            h3 = __shfl_sync(FULL, ht, base+3);
            dcur = dnext;
        }
        return;
    }

    // ================= rbf + qk tile role: 128x128 tile per block =================
    __shared__ __align__(16) float xs[32][132];   // k-major x tile
    __shared__ __align__(16) float ss[32][132];   // k-major s tile
    __shared__ float xrow[128][10];               // cos u[4], sin u[4], ||x||^2
    __shared__ float srow[128][10];               // cos v[4], sin v[4], ||s||^2

    int tile = blockIdx.x - LSTM_BLOCKS;
    int mt = tile >> 3;
    int nt = tile & 7;
    int m0 = mt * 128;
    int n0 = nt * 128;
    int tid = threadIdx.x;

    {   // load both tiles transposed into smem (coalesced gmem reads)
        int rbase = tid >> 3;          // 0..31
        int kc    = (tid & 7) * 4;     // k chunk
        #pragma unroll
        for (int pass=0; pass<4; pass++){
            int r = rbase + pass*32;
            float4 v = *(const float4*)(x  + (size_t)(m0 + r)*DFEAT + kc);
            xs[kc+0][r]=v.x; xs[kc+1][r]=v.y; xs[kc+2][r]=v.z; xs[kc+3][r]=v.w;
            float4 u = *(const float4*)(sv + (size_t)(n0 + r)*DFEAT + kc);
            ss[kc+0][r]=u.x; ss[kc+1][r]=u.y; ss[kc+2][r]=u.z; ss[kc+3][r]=u.w;
        }
    }
    __syncthreads();

    {   // per-row factors: norms + fast sincos((feat + qkp)/2)
        int r = tid & 127;
        float (*rowArr)[10]  = (tid < 128) ? xrow : srow;
        float (*tileArr)[132] = (tid < 128) ? xs : ss;
        float nrm = 0.f;
        #pragma unroll
        for (int k=0;k<32;k++){ float v = tileArr[k][r]; nrm = fmaf(v,v,nrm); }
        #pragma unroll
        for (int w=0; w<4; w++){
            float th = fmaf(tileArr[w][r], 0.5f, qkp[w]*0.5f);
            float s_, c_;
            __sincosf(th, &s_, &c_);
            rowArr[r][w]   = c_;
            rowArr[r][4+w] = s_;
        }
        rowArr[r][8] = nrm;
    }
    __syncthreads();

    int tx = tid & 15;        // 16 col-groups
    int ty = tid >> 4;        // 16 row-groups
    float4 acc[2][4][2];
    #pragma unroll
    for (int ii=0; ii<2; ii++)
        #pragma unroll
        for (int r=0; r<4; r++)
            #pragma unroll
            for (int jj=0; jj<2; jj++)
                acc[ii][r][jj] = make_float4(0.f,0.f,0.f,0.f);

    #pragma unroll 8
    for (int k=0; k<32; k++){
        const float4* xr = (const float4*)xs[k];
        const float4* sr = (const float4*)ss[k];
        float4 a0 = xr[ty];
        float4 a1 = xr[ty+16];
        float4 b0 = sr[tx];
        float4 b1 = sr[tx+16];
        fma4(acc[0][0][0], a0.x, b0); fma4(acc[0][0][1], a0.x, b1);
        fma4(acc[0][1][0], a0.y, b0); fma4(acc[0][1][1], a0.y, b1);
        fma4(acc[0][2][0], a0.z, b0); fma4(acc[0][2][1], a0.z, b1);
        fma4(acc[0][3][0], a0.w, b0); fma4(acc[0][3][1], a0.w, b1);
        fma4(acc[1][0][0], a1.x, b0); fma4(acc[1][0][1], a1.x, b1);
        fma4(acc[1][1][0], a1.y, b0); fma4(acc[1][1][1], a1.y, b1);
        fma4(acc[1][2][0], a1.z, b0); fma4(acc[1][2][1], a1.z, b1);
        fma4(acc[1][3][0], a1.w, b0); fma4(acc[1][3][1], a1.w, b1);
    }

    float* rbf_out = out + RBF_OFF;
    float* qk_out  = out + QK_OFF;
    const int ncol0 = n0 + tx*4;

    // ---- phase 1: rbf = exp(2*dot - ||x||^2 - ||s||^2) ----
    {
        float snA[4], snB[4];
        #pragma unroll
        for (int c=0;c<4;c++){ snA[c]=srow[tx*4+c][8]; snB[c]=srow[tx*4+c+64][8]; }
        #pragma unroll
        for (int ii=0; ii<2; ii++){
            #pragma unroll
            for (int r=0; r<4; r++){
                int mi = ty*4 + r + 64*ii;
                float xn = xrow[mi][8];
                int m = m0 + mi;
                float4 o0, o1;
                o0.x = fast_exp(fmaf(2.f, acc[ii][r][0].x, -(xn+snA[0])));
                o0.y = fast_exp(fmaf(2.f, acc[ii][r][0].y, -(xn+snA[1])));
                o0.z = fast_exp(fmaf(2.f, acc[ii][r][0].z, -(xn+snA[2])));
                o0.w = fast_exp(fmaf(2.f, acc[ii][r][0].w, -(xn+snA[3])));
                o1.x = fast_exp(fmaf(2.f, acc[ii][r][1].x, -(xn+snB[0])));
                o1.y = fast_exp(fmaf(2.f, acc[ii][r][1].y, -(xn+snB[1])));
                o1.z = fast_exp(fmaf(2.f, acc[ii][r][1].z, -(xn+snB[2])));
                o1.w = fast_exp(fmaf(2.f, acc[ii][r][1].w, -(xn+snB[3])));
                *(float4*)(rbf_out + (size_t)m*NSUP + ncol0)      = o0;
                *(float4*)(rbf_out + (size_t)m*NSUP + ncol0 + 64) = o1;
            }
        }
    }

    // ---- phase 2: qk[m,n] = | prod_w cos(u_mw + v_nw) | ----
    {
        float cvA[4][4], svA[4][4], cvB[4][4], svB[4][4];
        #pragma unroll
        for (int c=0;c<4;c++){
            #pragma unroll
            for (int w=0;w<4;w++){
                cvA[c][w]=srow[tx*4+c][w];    svA[c][w]=srow[tx*4+c][4+w];
                cvB[c][w]=srow[tx*4+c+64][w]; svB[c][w]=srow[tx*4+c+64][4+w];
            }
        }
        #pragma unroll
        for (int ii=0; ii<2; ii++){
            #pragma unroll
            for (int r=0; r<4; r++){
                int mi = ty*4 + r + 64*ii;
                float cu[4], su[4];
                #pragma unroll
                for (int w=0;w<4;w++){ cu[w]=xrow[mi][w]; su[w]=xrow[mi][4+w]; }
                int m = m0 + mi;
                float q0[4], q1[4];
                #pragma unroll
                for (int c=0;c<4;c++){
                    float t0 = fmaf(cu[0], cvA[c][0], -(su[0]*svA[c][0]));
                    float t1 = fmaf(cu[1], cvA[c][1], -(su[1]*svA[c][1]));
                    float t2 = fmaf(cu[2], cvA[c][2], -(su[2]*svA[c][2]));
                    float t3 = fmaf(cu[3], cvA[c][3], -(su[3]*svA[c][3]));
                    q0[c] = fabsf((t0*t1)*(t2*t3));
                    float u0 = fmaf(cu[0], cvB[c][0], -(su[0]*svB[c][0]));
                    float u1 = fmaf(cu[1], cvB[c][1], -(su[1]*svB[c][1]));
                    float u2 = fmaf(cu[2], cvB[c][2], -(su[2]*svB[c][2]));
                    float u3 = fmaf(cu[3], cvB[c][3], -(su[3]*svB[c][3]));
                    q1[c] = fabsf((u0*u1)*(u2*u3));
                }
                *(float4*)(qk_out + (size_t)m*NSUP + ncol0)      = make_float4(q0[0],q0[1],q0[2],q0[3]);
                *(float4*)(qk_out + (size_t)m*NSUP + ncol0 + 64) = make_float4(q1[0],q1[1],q1[2],q1[3]);
            }
        }
    }
}

extern "C" void kernel_launch(void* const* d_in, const int* in_sizes, int n_in,
                              void* d_out, int out_size)
{
    const float* x   = (const float*)d_in[0];
    const float* sv  = (const float*)d_in[1];
    const float* Wf  = (const float*)d_in[2];
    const float* bf  = (const float*)d_in[3];
    const float* Wi  = (const float*)d_in[4];
    const float* bi  = (const float*)d_in[5];
    const float* Wu  = (const float*)d_in[6];
    const float* bu  = (const float*)d_in[7];
    const float* Wo  = (const float*)d_in[8];
    const float* bo  = (const float*)d_in[9];
    const float* pf  = (const float*)d_in[10];
    const float* pi_ = (const float*)d_in[11];
    const float* pu  = (const float*)d_in[12];
    const float* po  = (const float*)d_in[13];
    const float* qkp = (const float*)d_in[14];

    hyb_kernel<<<NBLOCKS, 256>>>(x, sv, Wf, bf, Wi, bi, Wu, bu, Wo, bo,
                                 pf, pi_, pu, po, qkp, (float*)d_out);
}

// round 4
// speedup vs baseline: 1.3047x; 1.1021x over previous
#include <cuda_runtime.h>

#define T_STEPS 128
#define BATCH   64
#define DFEAT   32
#define NSUP    1024
#define MROWS   8192   // T_STEPS*BATCH
#define LSTM_BLOCKS 16
#define TILE_BLOCKS 256            // each handles 2 N-adjacent 128x128 tiles
#define NBLOCKS (LSTM_BLOCKS + TILE_BLOCKS)

#define OUTS_OFF 0
#define RBF_OFF  32768
#define QK_OFF   (32768 + MROWS*NSUP)

typedef unsigned long long u64;

__device__ __forceinline__ float tanh_hw(float z){
    float r;
    asm("tanh.approx.f32 %0, %1;" : "=f"(r) : "f"(z));
    return r;
}
__device__ __forceinline__ float sigm_hw(float z){
    return fmaf(0.5f, tanh_hw(0.5f*z), 0.5f);
}

// ---- packed fp32x2 helpers (Blackwell) ----
__device__ __forceinline__ u64 pack2(float lo, float hi){
    u64 r;
    asm("mov.b64 %0, {%1,%2};" : "=l"(r) : "f"(lo), "f"(hi));
    return r;
}
__device__ __forceinline__ u64 fma2_(u64 a, u64 b, u64 c){
    u64 d;
    asm("fma.rn.f32x2 %0, %1, %2, %3;" : "=l"(d) : "l"(a), "l"(b), "l"(c));
    return d;
}
__device__ __forceinline__ u64 mul2_(u64 a, u64 b){
    u64 d;
    asm("mul.rn.f32x2 %0, %1, %2;" : "=l"(d) : "l"(a), "l"(b));
    return d;
}
__device__ __forceinline__ u64 add2_(u64 a, u64 b){
    u64 d;
    asm("add.rn.f32x2 %0, %1, %2;" : "=l"(d) : "l"(a), "l"(b));
    return d;
}

// packed exp: all FMA/ALU, no MUFU. Underflow clamps to 0 via exponent max().
__device__ __forceinline__ u64 fexp2(u64 x2){
    u64 t = fma2_(x2, pack2(1.4426950408889634f,1.4426950408889634f),
                      pack2(12582912.0f,12582912.0f));
    u64 n = add2_(t, pack2(-12582912.0f,-12582912.0f));
    u64 f = fma2_(n, pack2(-0.693147182464599609375f,-0.693147182464599609375f), x2);
    f = fma2_(n, pack2(1.9046542743e-9f,1.9046542743e-9f), f);
    u64 z = mul2_(f, f);
    u64 p = pack2(1.9875691500E-4f, 1.9875691500E-4f);
    p = fma2_(p, f, pack2(1.3981999507E-3f,1.3981999507E-3f));
    p = fma2_(p, f, pack2(8.3334519073E-3f,8.3334519073E-3f));
    p = fma2_(p, f, pack2(4.1665795894E-2f,4.1665795894E-2f));
    p = fma2_(p, f, pack2(1.6666665459E-1f,1.6666665459E-1f));
    p = fma2_(p, f, pack2(5.0000001201E-1f,5.0000001201E-1f));
    p = fma2_(p, z, f);
    p = add2_(p, pack2(1.0f,1.0f));
    int blo, bhi;
    asm("mov.b64 {%0,%1}, %2;" : "=r"(blo), "=r"(bhi) : "l"(t));
    const int K = 127 - 0x4B400000;
    int elo = max(blo + K, 0) << 23;
    int ehi = max(bhi + K, 0) << 23;
    u64 s2 = pack2(__int_as_float(elo), __int_as_float(ehi));
    return mul2_(p, s2);
}

__global__ __launch_bounds__(256, 2)
void hyb_kernel(const float* __restrict__ x,
                const float* __restrict__ sv,
                const float* __restrict__ Wf, const float* __restrict__ bf,
                const float* __restrict__ Wi, const float* __restrict__ bi,
                const float* __restrict__ Wu, const float* __restrict__ bu,
                const float* __restrict__ Wo, const float* __restrict__ bo,
                const float* __restrict__ pf, const float* __restrict__ pi,
                const float* __restrict__ pu, const float* __restrict__ po,
                const float* __restrict__ qkp,
                float* __restrict__ out)
{
    if (blockIdx.x < LSTM_BLOCKS) {
        // ================= LSTM role: one warp per batch element =================
        int warp = threadIdx.x >> 5;
        if (warp >= 4) return;
        int lane = threadIdx.x & 31;
        int b    = blockIdx.x * 4 + warp;
        int sl   = lane & 15;
        int g    = sl >> 2;   // 0=f 1=i 2=u 3=o
        int w    = sl & 3;    // wire / hidden index

        const float* W  = (g==0)?Wf:(g==1)?Wi:(g==2)?Wu:Wo;
        const float* bb = (g==0)?bf:(g==1)?bi:(g==2)?bu:bo;
        const float* pp = (g==0)?pf:(g==1)?pi:(g==2)?pu:po;

        float wx[32];
        #pragma unroll
        for (int d=0; d<32; d++) wx[d] = W[w*36 + d];
        float wh0 = W[w*36+32], wh1 = W[w*36+33], wh2 = W[w*36+34], wh3 = W[w*36+35];
        float bias = bb[w] + pp[w];   // fold param angle into bias (RX compose)

        float h0=0.f,h1=0.f,h2=0.f,h3=0.f,cst=0.f;
        const unsigned FULL = 0xffffffffu;

        float dcur;
        {
            const float4* xp = (const float4*)(x + (size_t)b*DFEAT);
            float s0=bias, s1=0.f, s2=0.f, s3=0.f;
            #pragma unroll
            for (int q=0;q<8;q++){
                float4 v = xp[q];
                s0 = fmaf(wx[4*q+0], v.x, s0);
                s1 = fmaf(wx[4*q+1], v.y, s1);
                s2 = fmaf(wx[4*q+2], v.z, s2);
                s3 = fmaf(wx[4*q+3], v.w, s3);
            }
            dcur = (s0+s1)+(s2+s3);
        }

        for (int t=0; t<T_STEPS; t++){
            float theta = dcur;
            theta = fmaf(wh0,h0,theta);
            theta = fmaf(wh1,h1,theta);
            theta = fmaf(wh2,h2,theta);
            theta = fmaf(wh3,h3,theta);
            float cth = __cosf(theta);

            float dnext = bias;
            if (t < T_STEPS-1){
                const float4* xp = (const float4*)(x + ((size_t)(t+1)*BATCH + b)*DFEAT);
                float s0=bias, s1=0.f, s2=0.f, s3=0.f;
                #pragma unroll
                for (int q=0;q<8;q++){
                    float4 v = __ldg(&xp[q]);
                    s0 = fmaf(wx[4*q+0], v.x, s0);
                    s1 = fmaf(wx[4*q+1], v.y, s1);
                    s2 = fmaf(wx[4*q+2], v.z, s2);
                    s3 = fmaf(wx[4*q+3], v.w, s3);
                }
                dnext = (s0+s1)+(s2+s3);
            }

            int base = lane & ~3;
            float c0 = __shfl_sync(FULL, cth, base+0);
            float c1 = __shfl_sync(FULL, cth, base+1);
            float c2 = __shfl_sync(FULL, cth, base+2);
            float c3 = __shfl_sync(FULL, cth, base+3);
            float p01  = c0*c1;
            float p012 = p01*c2;
            float z = (w==0) ? c1*c2*c3 : (w==1) ? p01 : (w==2) ? p012 : p012*c3;
            float val = (g==2) ? tanh_hw(z) : sigm_hw(z);

            int hb = lane & 16;
            float fv = __shfl_sync(FULL, val, hb + 0  + w);
            float iv = __shfl_sync(FULL, val, hb + 4  + w);
            float uv = __shfl_sync(FULL, val, hb + 8  + w);
            float ov = __shfl_sync(FULL, val, hb + 12 + w);

            cst = fmaf(fv, cst, iv*uv);
            float ht = ov * tanh_hw(cst);
            if (lane < 4) out[OUTS_OFF + t*(BATCH*4) + b*4 + w] = ht;

            h0 = __shfl_sync(FULL, ht, base+0);
            h1 = __shfl_sync(FULL, ht, base+1);
            h2 = __shfl_sync(FULL, ht, base+2);
            h3 = __shfl_sync(FULL, ht, base+3);
            dcur = dnext;
        }
        return;
    }

    // ===== rbf + qk role: each block does 2 N-adjacent 128x128 tiles =====
    __shared__ __align__(16) float xs[32][132];   // k-major x tile (reused both subs)
    __shared__ __align__(16) float ss[32][132];   // k-major s tile (per sub)
    __shared__ float xrow[128][10];               // cos u, sin u, ||x||^2
    __shared__ float srow[128][10];               // cos v, NEG sin v, ||s||^2

    int bid2 = blockIdx.x - LSTM_BLOCKS;   // 0..255
    int mt = bid2 >> 2;                    // 0..63
    int np = bid2 & 3;                     // 0..3   -> nt = 2*np + sub
    int m0 = mt * 128;
    int tid = threadIdx.x;
    int rbase = tid >> 3;
    int kc    = (tid & 7) * 4;

    {   // load x tile transposed (once)
        #pragma unroll
        for (int pass=0; pass<4; pass++){
            int r = rbase + pass*32;
            float4 v = *(const float4*)(x + (size_t)(m0 + r)*DFEAT + kc);
            xs[kc+0][r]=v.x; xs[kc+1][r]=v.y; xs[kc+2][r]=v.z; xs[kc+3][r]=v.w;
        }
    }
    if (tid < 128){   // xrow straight from gmem (independent of xs)
        const float4* xp = (const float4*)(x + (size_t)(m0 + tid)*DFEAT);
        float4 v0 = xp[0];
        float nrm = 0.f;
        #pragma unroll
        for (int q=0;q<8;q++){
            float4 v = xp[q];
            nrm = fmaf(v.x,v.x,nrm); nrm = fmaf(v.y,v.y,nrm);
            nrm = fmaf(v.z,v.z,nrm); nrm = fmaf(v.w,v.w,nrm);
        }
        float fw[4] = {v0.x, v0.y, v0.z, v0.w};
        #pragma unroll
        for (int w=0; w<4; w++){
            float th = fmaf(fw[w], 0.5f, qkp[w]*0.5f);
            float s_, c_;
            __sincosf(th, &s_, &c_);
            xrow[tid][w]   = c_;
            xrow[tid][4+w] = s_;
        }
        xrow[tid][8] = nrm;
    }

    int tx = tid & 15;
    int ty = tid >> 4;
    float* rbf_out = out + RBF_OFF;
    float* qk_out  = out + QK_OFF;
    const u64 TWO2 = pack2(2.0f, 2.0f);

    for (int sub = 0; sub < 2; sub++){
        int n0 = (np*2 + sub) * 128;
        __syncthreads();   // sub0: xrow/xs writers done; sub1: prev readers done
        {   // load s tile transposed
            #pragma unroll
            for (int pass=0; pass<4; pass++){
                int r = rbase + pass*32;
                float4 u = *(const float4*)(sv + (size_t)(n0 + r)*DFEAT + kc);
                ss[kc+0][r]=u.x; ss[kc+1][r]=u.y; ss[kc+2][r]=u.z; ss[kc+3][r]=u.w;
            }
        }
        if (tid < 128){   // srow from gmem (sin stored NEGATED)
            const float4* sp = (const float4*)(sv + (size_t)(n0 + tid)*DFEAT);
            float4 v0 = sp[0];
            float nrm = 0.f;
            #pragma unroll
            for (int q=0;q<8;q++){
                float4 v = sp[q];
                nrm = fmaf(v.x,v.x,nrm); nrm = fmaf(v.y,v.y,nrm);
                nrm = fmaf(v.z,v.z,nrm); nrm = fmaf(v.w,v.w,nrm);
            }
            float fw[4] = {v0.x, v0.y, v0.z, v0.w};
            #pragma unroll
            for (int w=0; w<4; w++){
                float th = fmaf(fw[w], 0.5f, qkp[w]*0.5f);
                float s_, c_;
                __sincosf(th, &s_, &c_);
                srow[tid][w]   = c_;
                srow[tid][4+w] = -s_;
            }
            srow[tid][8] = nrm;
        }
        __syncthreads();

        // ---- main GEMM loop, packed f32x2 along N ----
        u64 acc2[2][4][2][2];   // [ii][row][jj(B-half)][pair]
        #pragma unroll
        for (int ii=0;ii<2;ii++)
            #pragma unroll
            for (int r=0;r<4;r++)
                #pragma unroll
                for (int jj=0;jj<2;jj++){ acc2[ii][r][jj][0]=0ull; acc2[ii][r][jj][1]=0ull; }

        #pragma unroll 8
        for (int k=0; k<32; k++){
            float4 a0 = ((const float4*)xs[k])[ty];
            float4 a1 = ((const float4*)xs[k])[ty+16];
            ulonglong2 B0 = ((const ulonglong2*)ss[k])[tx];
            ulonglong2 B1 = ((const ulonglong2*)ss[k])[tx+16];
            u64 aa;
            aa = pack2(a0.x,a0.x);
            acc2[0][0][0][0]=fma2_(aa,B0.x,acc2[0][0][0][0]); acc2[0][0][0][1]=fma2_(aa,B0.y,acc2[0][0][0][1]);
            acc2[0][0][1][0]=fma2_(aa,B1.x,acc2[0][0][1][0]); acc2[0][0][1][1]=fma2_(aa,B1.y,acc2[0][0][1][1]);
            aa = pack2(a0.y,a0.y);
            acc2[0][1][0][0]=fma2_(aa,B0.x,acc2[0][1][0][0]); acc2[0][1][0][1]=fma2_(aa,B0.y,acc2[0][1][0][1]);
            acc2[0][1][1][0]=fma2_(aa,B1.x,acc2[0][1][1][0]); acc2[0][1][1][1]=fma2_(aa,B1.y,acc2[0][1][1][1]);
            aa = pack2(a0.z,a0.z);
            acc2[0][2][0][0]=fma2_(aa,B0.x,acc2[0][2][0][0]); acc2[0][2][0][1]=fma2_(aa,B0.y,acc2[0][2][0][1]);
            acc2[0][2][1][0]=fma2_(aa,B1.x,acc2[0][2][1][0]); acc2[0][2][1][1]=fma2_(aa,B1.y,acc2[0][2][1][1]);
            aa = pack2(a0.w,a0.w);
            acc2[0][3][0][0]=fma2_(aa,B0.x,acc2[0][3][0][0]); acc2[0][3][0][1]=fma2_(aa,B0.y,acc2[0][3][0][1]);
            acc2[0][3][1][0]=fma2_(aa,B1.x,acc2[0][3][1][0]); acc2[0][3][1][1]=fma2_(aa,B1.y,acc2[0][3][1][1]);
            aa = pack2(a1.x,a1.x);
            acc2[1][0][0][0]=fma2_(aa,B0.x,acc2[1][0][0][0]); acc2[1][0][0][1]=fma2_(aa,B0.y,acc2[1][0][0][1]);
            acc2[1][0][1][0]=fma2_(aa,B1.x,acc2[1][0][1][0]); acc2[1][0][1][1]=fma2_(aa,B1.y,acc2[1][0][1][1]);
            aa = pack2(a1.y,a1.y);
            acc2[1][1][0][0]=fma2_(aa,B0.x,acc2[1][1][0][0]); acc2[1][1][0][1]=fma2_(aa,B0.y,acc2[1][1][0][1]);
            acc2[1][1][1][0]=fma2_(aa,B1.x,acc2[1][1][1][0]); acc2[1][1][1][1]=fma2_(aa,B1.y,acc2[1][1][1][1]);
            aa = pack2(a1.z,a1.z);
            acc2[1][2][0][0]=fma2_(aa,B0.x,acc2[1][2][0][0]); acc2[1][2][0][1]=fma2_(aa,B0.y,acc2[1][2][0][1]);
            acc2[1][2][1][0]=fma2_(aa,B1.x,acc2[1][2][1][0]); acc2[1][2][1][1]=fma2_(aa,B1.y,acc2[1][2][1][1]);
            aa = pack2(a1.w,a1.w);
            acc2[1][3][0][0]=fma2_(aa,B0.x,acc2[1][3][0][0]); acc2[1][3][0][1]=fma2_(aa,B0.y,acc2[1][3][0][1]);
            acc2[1][3][1][0]=fma2_(aa,B1.x,acc2[1][3][1][0]); acc2[1][3][1][1]=fma2_(aa,B1.y,acc2[1][3][1][1]);
        }

        const int ncol0 = n0 + tx*4;

        // ---- rbf epilogue (packed): exp(2*dot - xn - sn) ----
        {
            u64 nsnA[2], nsnB[2];
            nsnA[0] = pack2(-srow[tx*4+0][8], -srow[tx*4+1][8]);
            nsnA[1] = pack2(-srow[tx*4+2][8], -srow[tx*4+3][8]);
            nsnB[0] = pack2(-srow[tx*4+64][8], -srow[tx*4+65][8]);
            nsnB[1] = pack2(-srow[tx*4+66][8], -srow[tx*4+67][8]);
            #pragma unroll
            for (int ii=0; ii<2; ii++){
                #pragma unroll
                for (int r=0; r<4; r++){
                    int mi = ty*4 + r + 64*ii;
                    float xn = xrow[mi][8];
                    u64 nxn2 = pack2(-xn, -xn);
                    int m = m0 + mi;
                    u64 e00 = fexp2(fma2_(acc2[ii][r][0][0], TWO2, add2_(nxn2, nsnA[0])));
                    u64 e01 = fexp2(fma2_(acc2[ii][r][0][1], TWO2, add2_(nxn2, nsnA[1])));
                    u64 e10 = fexp2(fma2_(acc2[ii][r][1][0], TWO2, add2_(nxn2, nsnB[0])));
                    u64 e11 = fexp2(fma2_(acc2[ii][r][1][1], TWO2, add2_(nxn2, nsnB[1])));
                    ulonglong2 st0; st0.x = e00; st0.y = e01;
                    ulonglong2 st1; st1.x = e10; st1.y = e11;
                    *(ulonglong2*)(rbf_out + (size_t)m*NSUP + ncol0)      = st0;
                    *(ulonglong2*)(rbf_out + (size_t)m*NSUP + ncol0 + 64) = st1;
                }
            }
        }

        // ---- qk epilogue (packed): |prod_w (cu*cv - su*sv)| ----
        {
            u64 cvA[2][4], nsvA[2][4], cvB[2][4], nsvB[2][4];
            #pragma unroll
            for (int p=0; p<2; p++){
                int c0 = tx*4 + 2*p, c1 = c0 + 1;
                #pragma unroll
                for (int w=0; w<4; w++){
                    cvA[p][w]  = pack2(srow[c0][w],    srow[c1][w]);
                    nsvA[p][w] = pack2(srow[c0][4+w],  srow[c1][4+w]);   // already negated
                    cvB[p][w]  = pack2(srow[c0+64][w], srow[c1+64][w]);
                    nsvB[p][w] = pack2(srow[c0+64][4+w], srow[c1+64][4+w]);
                }
            }
            const u64 ABSM = 0x7FFFFFFF7FFFFFFFull;
            #pragma unroll
            for (int ii=0; ii<2; ii++){
                #pragma unroll
                for (int r=0; r<4; r++){
                    int mi = ty*4 + r + 64*ii;
                    int m = m0 + mi;
                    u64 cu2[4], su2[4];
                    #pragma unroll
                    for (int w=0; w<4; w++){
                        float cu = xrow[mi][w], su = xrow[mi][4+w];
                        cu2[w] = pack2(cu,cu); su2[w] = pack2(su,su);
                    }
                    u64 qA[2], qB[2];
                    #pragma unroll
                    for (int p=0; p<2; p++){
                        u64 t0 = fma2_(cu2[0], cvA[p][0], mul2_(su2[0], nsvA[p][0]));
                        u64 t1 = fma2_(cu2[1], cvA[p][1], mul2_(su2[1], nsvA[p][1]));
                        u64 t2 = fma2_(cu2[2], cvA[p][2], mul2_(su2[2], nsvA[p][2]));
                        u64 t3 = fma2_(cu2[3], cvA[p][3], mul2_(su2[3], nsvA[p][3]));
                        qA[p] = mul2_(mul2_(t0,t1), mul2_(t2,t3)) & ABSM;
                        u64 v0 = fma2_(cu2[0], cvB[p][0], mul2_(su2[0], nsvB[p][0]));
                        u64 v1 = fma2_(cu2[1], cvB[p][1], mul2_(su2[1], nsvB[p][1]));
                        u64 v2 = fma2_(cu2[2], cvB[p][2], mul2_(su2[2], nsvB[p][2]));
                        u64 v3 = fma2_(cu2[3], cvB[p][3], mul2_(su2[3], nsvB[p][3]));
                        qB[p] = mul2_(mul2_(v0,v1), mul2_(v2,v3)) & ABSM;
                    }
                    ulonglong2 st0; st0.x = qA[0]; st0.y = qA[1];
                    ulonglong2 st1; st1.x = qB[0]; st1.y = qB[1];
                    *(ulonglong2*)(qk_out + (size_t)m*NSUP + ncol0)      = st0;
                    *(ulonglong2*)(qk_out + (size_t)m*NSUP + ncol0 + 64) = st1;
                }
            }
        }
    }
}

extern "C" void kernel_launch(void* const* d_in, const int* in_sizes, int n_in,
                              void* d_out, int out_size)
{
    const float* x   = (const float*)d_in[0];
    const float* sv  = (const float*)d_in[1];
    const float* Wf  = (const float*)d_in[2];
    const float* bf  = (const float*)d_in[3];
    const float* Wi  = (const float*)d_in[4];
    const float* bi  = (const float*)d_in[5];
    const float* Wu  = (const float*)d_in[6];
    const float* bu  = (const float*)d_in[7];
    const float* Wo  = (const float*)d_in[8];
    const float* bo  = (const float*)d_in[9];
    const float* pf  = (const float*)d_in[10];
    const float* pi_ = (const float*)d_in[11];
    const float* pu  = (const float*)d_in[12];
    const float* po  = (const float*)d_in[13];
    const float* qkp = (const float*)d_in[14];

    hyb_kernel<<<NBLOCKS, 256>>>(x, sv, Wf, bf, Wi, bi, Wu, bu, Wo, bo,
                                 pf, pi_, pu, po, qkp, (float*)d_out);
}